// round 14
// baseline (speedup 1.0000x reference)
#include <cuda_runtime.h>
#include <cuda_bf16.h>
#include <math.h>

#define Bb 64
#define Nn 16
#define Cc 16
#define Tt 256
#define DH 128
#define DIN 136
#define DP 128
#define TOUT 32
#define BN 1024

typedef unsigned long long ull;

__device__ float g_Hc[BN * Tt * DH];           // [m][t][128]
__device__ __nv_bfloat16 g_Kh[BN * Tt * DP];   // [m][t][d] bf16
__device__ __nv_bfloat16 g_Vh[BN * Tt * DP];   // [m][t][d] bf16
__device__ float g_A [Bb * Nn * Nn];
__device__ float g_WnT[DIN * DP];
__device__ float g_WsT[DIN * DP];
__device__ float g_WkT[DP * DP];
__device__ float g_WvT[DP * DP];
__device__ float g_h  [BN * DP];
__device__ float g_y  [BN * Cc];
__device__ float g_ymix[BN * Cc];
__device__ float g_ctx [BN * DP];

// ---- f32x2 helpers ----
__device__ __forceinline__ ull dup2(float v) {
    ull r; asm("mov.b64 %0, {%1, %1};" : "=l"(r) : "f"(v)); return r;
}
__device__ __forceinline__ void fma2(ull& d, ull a, ull b) {
    asm("fma.rn.f32x2 %0, %1, %2, %0;" : "+l"(d) : "l"(a), "l"(b));
}
__device__ __forceinline__ float2 unp2(ull v) {
    float2 r; asm("mov.b64 {%0, %1}, %2;" : "=f"(r.x), "=f"(r.y) : "l"(v)); return r;
}
__device__ __forceinline__ unsigned bf2u(float a, float b) {
    __nv_bfloat162 h = __floats2bfloat162_rn(a, b);
    return *(unsigned*)&h;
}
__device__ __forceinline__ float2 bfu2f(unsigned u) {
    __nv_bfloat162 h = *(__nv_bfloat162*)&u;
    return __bfloat1622float2(h);
}

__device__ __forceinline__ float sigmoidf_(float x) { return 1.f / (1.f + expf(-x)); }
__device__ __forceinline__ float softplusf_(float x) {
    return x > 0.f ? x + log1pf(expf(-x)) : log1pf(expf(x));
}
__device__ __forceinline__ float block_sum256(float v, float* sbuf, int tid) {
    #pragma unroll
    for (int o = 16; o; o >>= 1) v += __shfl_xor_sync(0xffffffffu, v, o);
    if ((tid & 31) == 0) sbuf[tid >> 5] = v;
    __syncthreads();
    float r = 0.f;
    #pragma unroll
    for (int w = 0; w < 8; w++) r += sbuf[w];
    __syncthreads();
    return r;
}

// ---- spectral norm of W_neigh ----
__global__ void spec_kernel(const float* __restrict__ W) {
    __shared__ float su[DP], sv[DIN], sred[8];
    int tid = threadIdx.x;
    if (tid < DP) su[tid] = rsqrtf((float)DP);
    __syncthreads();
    for (int it = 0; it < 15; it++) {
        float vv = 0.f;
        if (tid < DIN)
            for (int i = 0; i < DP; i++) vv += W[i * DIN + tid] * su[i];
        float nv = sqrtf(block_sum256((tid < DIN) ? vv * vv : 0.f, sred, tid));
        if (tid < DIN) sv[tid] = vv / nv;
        __syncthreads();
        float uu = 0.f;
        if (tid < DP)
            for (int j = 0; j < DIN; j++) uu += W[tid * DIN + j] * sv[j];
        float nu = sqrtf(block_sum256((tid < DP) ? uu * uu : 0.f, sred, tid));
        if (tid < DP) su[tid] = uu / nu;
        __syncthreads();
    }
    float p = 0.f;
    if (tid < DP) {
        float t = 0.f;
        for (int j = 0; j < DIN; j++) t += W[tid * DIN + j] * sv[j];
        p = su[tid] * t;
    }
    float sigma = block_sum256(p, sred, tid);
    float inv = 1.f / sigma;
    for (int idx = tid; idx < DIN * DP; idx += 256) {
        int k = idx >> 7, d = idx & 127;
        g_WnT[idx] = W[d * DIN + k] * inv;
    }
}

__global__ void prep_kernel(const float* __restrict__ Ws, const float* __restrict__ Wk,
                            const float* __restrict__ Wv) {
    int idx = blockIdx.x * 256 + threadIdx.x;
    if (idx < DIN * DP) { int k = idx >> 7, d = idx & 127; g_WsT[idx] = Ws[d * DIN + k]; }
    if (idx < DP * DP)  { int k = idx >> 7, d = idx & 127; g_WkT[idx] = Wk[d * DP + k];
                          g_WvT[idx] = Wv[d * DP + k]; }
    if (idx < BN * Cc)  g_y[idx] = 0.f;
}

__global__ void graph_kernel(const float* __restrict__ S, const float* __restrict__ G,
                             const int* __restrict__ phases) {
    int b = blockIdx.x, tid = threadIdx.x;
    int i = tid >> 4, j = tid & 15;
    int p = phases[b];
    const float* Sp = S + p * 256;
    float denom = 0.f;
    #pragma unroll
    for (int jj = 0; jj < 16; jj++) if (jj != i) denom += fabsf(Sp[i * 16 + jj]);
    denom = fmaxf(denom, 1e-6f);
    float gsum = 0.f;
    #pragma unroll
    for (int ii = 0; ii < 16; ii++) gsum += softplusf_(G[p * 16 + ii]) + 1e-6f;
    gsum = fmaxf(gsum, 1e-6f);
    float gi = (softplusf_(G[p * 16 + i]) + 1e-6f) * (16.0f / gsum);
    float sz = (i == j) ? 0.f : Sp[i * 16 + j];
    g_A[b * 256 + tid] = sz / denom * gi;
}

// ---- GRU + LN: 8 sequences per block ----
#define QB 8
#define GRU_XQ   (Tt * 16)
#define GRU_SMEM ((QB * GRU_XQ + 384 * 20) * 4)

__global__ void __launch_bounds__(384, 1)
gru_kernel(const float* __restrict__ X, const float* __restrict__ Wih,
           const float* __restrict__ Whh, const float* __restrict__ bih,
           const float* __restrict__ bhh, const float* __restrict__ lng,
           const float* __restrict__ lnb) {
    extern __shared__ __align__(16) float dyn[];
    float* x_s   = dyn;
    float* wih_s = dyn + QB * GRU_XQ;
    __shared__ __align__(16) float h_s[QB][DH];
    __shared__ float sGx[QB][384];
    __shared__ float sGh[QB][384];
    __shared__ float spart[QB][8];

    int n = blockIdx.x & 15, bg = blockIdx.x >> 4;
    int g = threadIdx.x;

    for (int idx = g; idx < QB * Cc * Tt; idx += 384) {
        int q = idx >> 12, r = idx & 4095;
        int c = r >> 8, t = r & 255;
        int m = (bg * QB + q) * 16 + n;
        x_s[q * GRU_XQ + t * 16 + c] = X[m * (Cc * Tt) + r];
    }
    for (int idx = g; idx < 384 * 16; idx += 384) {
        int gg = idx >> 4, c = idx & 15;
        wih_s[gg * 20 + c] = Wih[n * 6144 + idx];
    }
    ull w2[64];
    {
        const ulonglong2* wp2 = (const ulonglong2*)(Whh + (n * 384 + g) * 128);
        #pragma unroll
        for (int k = 0; k < 32; k++) {
            ulonglong2 v = wp2[k];
            w2[2 * k] = v.x; w2[2 * k + 1] = v.y;
        }
    }
    float bi = bih[n * 384 + g], bh = bhh[n * 384 + g];
    float lg = 1.f, lbv = 0.f;
    if (g < 128) { lg = lng[g]; lbv = lnb[g]; }
    if (g < 128) {
        #pragma unroll
        for (int q = 0; q < QB; q++) h_s[q][g] = 0.f;
    }
    __syncthreads();

    for (int t = 0; t < Tt; t++) {
        #pragma unroll
        for (int q = 0; q < QB; q++) {
            ull hA = 0, hB = 0;
            const ulonglong2* h2 = (const ulonglong2*)h_s[q];
            #pragma unroll
            for (int k = 0; k < 32; k++) {
                ulonglong2 hv = h2[k];
                fma2(hA, w2[2 * k],     hv.x);
                fma2(hB, w2[2 * k + 1], hv.y);
            }
            ull axA = 0, axB = 0;
            const ulonglong2* xr = (const ulonglong2*)(x_s + q * GRU_XQ + t * 16);
            const ulonglong2* wi = (const ulonglong2*)(wih_s + g * 20);
            #pragma unroll
            for (int k = 0; k < 4; k++) {
                ulonglong2 wv = wi[k], xv = xr[k];
                fma2(axA, wv.x, xv.x);
                fma2(axB, wv.y, xv.y);
            }
            float2 fa = unp2(hA), fb = unp2(hB);
            float2 xa = unp2(axA), xb = unp2(axB);
            sGh[q][g] = bh + ((fa.x + fa.y) + (fb.x + fb.y));
            sGx[q][g] = bi + ((xa.x + xa.y) + (xb.x + xb.y));
        }
        __syncthreads();
        float hn[QB];
        if (g < 128) {
            float s1[QB], s2[QB];
            #pragma unroll
            for (int q = 0; q < QB; q++) {
                float r  = sigmoidf_(sGx[q][g] + sGh[q][g]);
                float z  = sigmoidf_(sGx[q][g + 128] + sGh[q][g + 128]);
                float nn = tanhf(sGx[q][g + 256] + r * sGh[q][g + 256]);
                float h0 = h_s[q][g];
                hn[q] = (1.f - z) * nn + z * h0;
                h_s[q][g] = hn[q];
                s1[q] = hn[q]; s2[q] = hn[q] * hn[q];
            }
            #pragma unroll
            for (int o = 16; o; o >>= 1) {
                #pragma unroll
                for (int q = 0; q < QB; q++) {
                    s1[q] += __shfl_down_sync(0xffffffffu, s1[q], o);
                    s2[q] += __shfl_down_sync(0xffffffffu, s2[q], o);
                }
            }
            if ((g & 31) == 0) {
                int wid = g >> 5;
                #pragma unroll
                for (int q = 0; q < QB; q++) {
                    spart[q][wid] = s1[q]; spart[q][4 + wid] = s2[q];
                }
            }
        }
        __syncthreads();
        if (g < 128) {
            #pragma unroll
            for (int q = 0; q < QB; q++) {
                float m1 = (spart[q][0]+spart[q][1]+spart[q][2]+spart[q][3]) * (1.f/128.f);
                float m2 = (spart[q][4]+spart[q][5]+spart[q][6]+spart[q][7]) * (1.f/128.f) - m1*m1;
                float inv = rsqrtf(m2 + 1e-5f);
                int m = (bg * QB + q) * 16 + n;
                g_Hc[(m * Tt + t) * DH + g] = (hn[q] - m1) * inv * lg + lbv;
            }
        }
    }
}

// ---- fused feature stage: 512 threads, 4x8 tile per thread ----
__device__ __forceinline__ void zeroacc4(ull acc2[4][4]) {
    #pragma unroll
    for (int r = 0; r < 4; r++) {
        #pragma unroll
        for (int c = 0; c < 4; c++) acc2[r][c] = 0ull;
    }
}

__device__ __forceinline__ void gemmf2_4(ull acc2[4][4], const float* sA, int lda,
                                         const float* sB, int kd, int R0, int C0) {
    #pragma unroll 2
    for (int k = 0; k < kd; k++) {
        ulonglong2 bA = *(const ulonglong2*)(sB + k * 128 + C0);
        ulonglong2 bB = *(const ulonglong2*)(sB + k * 128 + C0 + 4);
        #pragma unroll
        for (int r = 0; r < 4; r++) {
            ull a2 = dup2(sA[(R0 + r) * lda + k]);
            fma2(acc2[r][0], a2, bA.x);
            fma2(acc2[r][1], a2, bA.y);
            fma2(acc2[r][2], a2, bB.x);
            fma2(acc2[r][3], a2, bB.y);
        }
    }
}

#define SH_LD 137
#define SZ_LD 136
#define SP_LD 132
#define FEAT_SMEM ((128*SH_LD + DIN*128 + 128*SP_LD + 256) * 4)

__global__ void __launch_bounds__(512, 1) feat_kernel(const float* __restrict__ tW,
                                                      const float* __restrict__ tb) {
    extern __shared__ float sm[];
    float* sH   = sm;
    float* sW   = sm + 128 * SH_LD;
    float* sP   = sW + DIN * 128;
    float* sA16 = sP + 128 * SP_LD;

    int b = blockIdx.x >> 5, tt = blockIdx.x & 31;
    int tid = threadIdx.x, tx = tid & 15, ty = tid >> 4;   // ty 0..31
    int R0 = ty * 4, C0 = tx * 8;
    int ig = ty >> 1;                 // region index of this tile's rows
    int tl0 = (ty & 1) * 4;           // first t-local row

    for (int idx = tid; idx < 128 * DIN; idx += 512) {
        int r = idx / DIN, c = idx - r * DIN;
        int n = r >> 3, tl = r & 7;
        float v;
        if (c < 128) {
            v = g_Hc[((b * 16 + n) * Tt + tt * 8 + tl) * DH + c];
        } else {
            float tv = (float)(tt * 8 + tl) * (1.f / 255.f);
            v = tanhf(tv * tW[c - 128] + tb[c - 128]);
        }
        sH[r * SH_LD + c] = v;
    }
    for (int idx = tid; idx < DIN * 128; idx += 512) sW[idx] = g_WnT[idx];
    if (tid < 256) sA16[tid] = g_A[b * 256 + tid];
    __syncthreads();

    ull acc2[4][4];
    // GEMM1: P1 = Hc @ Wn^T -> sP
    zeroacc4(acc2);
    gemmf2_4(acc2, sH, SH_LD, sW, DIN, R0, C0);
    __syncthreads();
    #pragma unroll
    for (int r = 0; r < 4; r++) {
        *(ulonglong2*)&sP[(R0+r)*SP_LD + C0]     = make_ulonglong2(acc2[r][0], acc2[r][1]);
        *(ulonglong2*)&sP[(R0+r)*SP_LD + C0 + 4] = make_ulonglong2(acc2[r][2], acc2[r][3]);
    }
    for (int idx = tid; idx < DIN * 128; idx += 512) sW[idx] = g_WsT[idx];
    __syncthreads();

    // GEMM2: self = Hc @ Ws^T ; mix with A ; leaky
    zeroacc4(acc2);
    gemmf2_4(acc2, sH, SH_LD, sW, DIN, R0, C0);
    {
        #pragma unroll
        for (int j = 0; j < 16; j++) {
            ull a2 = dup2(sA16[ig * 16 + j]);
            #pragma unroll
            for (int r = 0; r < 4; r++) {
                const float* pr = &sP[(j * 8 + tl0 + r) * SP_LD + C0];
                ulonglong2 p0 = *(const ulonglong2*)pr;
                ulonglong2 p1 = *(const ulonglong2*)(pr + 4);
                fma2(acc2[r][0], a2, p0.x);
                fma2(acc2[r][1], a2, p0.y);
                fma2(acc2[r][2], a2, p1.x);
                fma2(acc2[r][3], a2, p1.y);
            }
        }
    }
    float accf[4][8];
    #pragma unroll
    for (int r = 0; r < 4; r++) {
        #pragma unroll
        for (int p = 0; p < 4; p++) {
            float2 v = unp2(acc2[r][p]);
            accf[r][2*p]   = v.x >= 0.f ? v.x : 0.1f * v.x;
            accf[r][2*p+1] = v.y >= 0.f ? v.y : 0.1f * v.y;
        }
    }
    __syncthreads();
    #pragma unroll
    for (int r = 0; r < 4; r++) {
        int row = R0 + r;
        *(float4*)&sH[row*SZ_LD + C0]     = make_float4(accf[r][0],accf[r][1],accf[r][2],accf[r][3]);
        *(float4*)&sH[row*SZ_LD + C0 + 4] = make_float4(accf[r][4],accf[r][5],accf[r][6],accf[r][7]);
        if (tt == 31 && tl0 + r == 7) {
            float* hp = g_h + (b * 16 + ig) * DP + C0;
            #pragma unroll
            for (int c = 0; c < 8; c++) hp[c] = accf[r][c];
        }
    }
    for (int idx = tid; idx < DP * DP; idx += 512) sW[idx] = g_WkT[idx];
    __syncthreads();

    // GEMM3: K = Z @ Wk^T -> direct bf16 write [m][t][d]
    zeroacc4(acc2);
    gemmf2_4(acc2, sH, SZ_LD, sW, DP, R0, C0);
    #pragma unroll
    for (int r = 0; r < 4; r++) {
        int mm = b * 16 + ig;
        int tg = tt * 8 + tl0 + r;
        float2 v0 = unp2(acc2[r][0]), v1 = unp2(acc2[r][1]);
        float2 v2 = unp2(acc2[r][2]), v3 = unp2(acc2[r][3]);
        uint4 o;
        o.x = bf2u(v0.x, v0.y);
        o.y = bf2u(v1.x, v1.y);
        o.z = bf2u(v2.x, v2.y);
        o.w = bf2u(v3.x, v3.y);
        *(uint4*)&g_Kh[(mm * Tt + tg) * DP + C0] = o;
    }
    __syncthreads();
    for (int idx = tid; idx < DP * DP; idx += 512) sW[idx] = g_WvT[idx];
    __syncthreads();

    // GEMM4: V = Z @ Wv^T -> direct bf16 write [m][t][d]
    zeroacc4(acc2);
    gemmf2_4(acc2, sH, SZ_LD, sW, DP, R0, C0);
    #pragma unroll
    for (int r = 0; r < 4; r++) {
        int mm = b * 16 + ig;
        int tg = tt * 8 + tl0 + r;
        float2 v0 = unp2(acc2[r][0]), v1 = unp2(acc2[r][1]);
        float2 v2 = unp2(acc2[r][2]), v3 = unp2(acc2[r][3]);
        uint4 o;
        o.x = bf2u(v0.x, v0.y);
        o.y = bf2u(v1.x, v1.y);
        o.z = bf2u(v2.x, v2.y);
        o.w = bf2u(v3.x, v3.y);
        *(uint4*)&g_Vh[(mm * Tt + tg) * DP + C0] = o;
    }
}

// ---- decoder: attention (coalesced warp-row scores) + y graph-mix ----
__global__ void __launch_bounds__(512) attn_kernel(const float* __restrict__ log_tau) {
    __shared__ __align__(16) float h_s[DP];
    __shared__ float al[Tt];
    __shared__ float sc[Tt];
    __shared__ float red[8], red2[8];
    __shared__ __align__(16) float part[32][132];
    int m = blockIdx.x, tid = threadIdx.x;
    int w = tid >> 5, lane = tid & 31;
    if (tid < DP) h_s[tid] = g_h[m * DP + tid];
    if (tid >= 256 && tid < 272) {
        int c = tid - 256, b = m >> 4, i = m & 15;
        float s = 0.f;
        #pragma unroll
        for (int j = 0; j < 16; j++) s += g_A[b * 256 + i * 16 + j] * g_y[(b * 16 + j) * Cc + c];
        g_ymix[m * Cc + c] = g_y[m * Cc + c] + 0.3f * s;
    }
    __syncthreads();
    {
        float h0 = h_s[lane * 4], h1 = h_s[lane * 4 + 1];
        float h2 = h_s[lane * 4 + 2], h3 = h_s[lane * 4 + 3];
        #pragma unroll 4
        for (int r = 0; r < 16; r++) {
            int t = w * 16 + r;
            uint2 kv = *(const uint2*)(g_Kh + (m * Tt + t) * DP + lane * 4);
            float2 a0 = bfu2f(kv.x), a1 = bfu2f(kv.y);
            float dot = a0.x * h0 + a0.y * h1 + a1.x * h2 + a1.y * h3;
            #pragma unroll
            for (int o = 16; o; o >>= 1) dot += __shfl_xor_sync(0xffffffffu, dot, o);
            if (lane == 0) sc[t] = dot;
        }
    }
    __syncthreads();
    float scale = expf(log_tau[0]);
    if (tid < 256) {
        float sv = sc[tid] * scale;
        sc[tid] = sv;
        float mx = sv;
        #pragma unroll
        for (int o = 16; o; o >>= 1) mx = fmaxf(mx, __shfl_xor_sync(0xffffffffu, mx, o));
        if ((tid & 31) == 0) red[tid >> 5] = mx;
    }
    __syncthreads();
    if (tid < 256) {
        float bmx = red[0];
        #pragma unroll
        for (int w2 = 1; w2 < 8; w2++) bmx = fmaxf(bmx, red[w2]);
        float ev = expf(sc[tid] - bmx);
        al[tid] = ev;
        float ss = ev;
        #pragma unroll
        for (int o = 16; o; o >>= 1) ss += __shfl_xor_sync(0xffffffffu, ss, o);
        if ((tid & 31) == 0) red2[tid >> 5] = ss;
    }
    __syncthreads();
    float tot = 0.f;
    #pragma unroll
    for (int w2 = 0; w2 < 8; w2++) tot += red2[w2];
    float inv = 1.f / tot;
    {
        int dsl = tid & 15, tch = tid >> 4;
        float acc[8];
        #pragma unroll
        for (int j = 0; j < 8; j++) acc[j] = 0.f;
        #pragma unroll
        for (int u = 0; u < 8; u++) {
            int t2 = tch * 8 + u;
            uint4 v = *(const uint4*)(g_Vh + (m * Tt + t2) * DP + dsl * 8);
            float a = al[t2];
            float2 f0 = bfu2f(v.x), f1 = bfu2f(v.y), f2 = bfu2f(v.z), f3 = bfu2f(v.w);
            acc[0] += a * f0.x; acc[1] += a * f0.y;
            acc[2] += a * f1.x; acc[3] += a * f1.y;
            acc[4] += a * f2.x; acc[5] += a * f2.y;
            acc[6] += a * f3.x; acc[7] += a * f3.y;
        }
        *(float4*)&part[tch][dsl * 8]     = make_float4(acc[0], acc[1], acc[2], acc[3]);
        *(float4*)&part[tch][dsl * 8 + 4] = make_float4(acc[4], acc[5], acc[6], acc[7]);
    }
    __syncthreads();
    if (tid < 128) {
        float c = 0.f;
        #pragma unroll
        for (int ch = 0; ch < 32; ch++) c += part[ch][tid];
        g_ctx[m * DP + tid] = c * inv;
    }
}

// ---- decoder: GRU cell + readout (f32x2) ----
__global__ void __launch_bounds__(384) cell_kernel(const float* __restrict__ Wihc,
                                                   const float* __restrict__ Whhc,
                                                   const float* __restrict__ bihc,
                                                   const float* __restrict__ bhhc,
                                                   const float* __restrict__ readW,
                                                   const float* __restrict__ readb,
                                                   const float* __restrict__ X,
                                                   float* __restrict__ out, int step) {
    __shared__ __align__(16) float inp[8 * 148];
    __shared__ __align__(16) float hprev[8 * 128];
    __shared__ float sX[384 * 8], sH2[384 * 8];
    __shared__ float shn[8 * 128];
    int m0 = blockIdx.x * 8, g = threadIdx.x;

    for (int idx = g; idx < 8 * 128; idx += 384) {
        int q = idx >> 7, d = idx & 127;
        inp[q * 148 + d] = g_ctx[(m0 + q) * DP + d];
        hprev[idx] = g_h[(m0 + q) * DP + d];
    }
    for (int idx = g; idx < 8 * 16; idx += 384) {
        int q = idx >> 4, c = idx & 15;
        inp[q * 148 + 128 + c] = g_ymix[(m0 + q) * Cc + c];
    }
    __syncthreads();

    ull aX2[8], aH2[8];
    #pragma unroll
    for (int q = 0; q < 8; q++) { aX2[q] = 0ull; aH2[q] = 0ull; }
    const ulonglong2* wr2 = (const ulonglong2*)(Wihc + g * 144);
    #pragma unroll 4
    for (int kk = 0; kk < 36; kk++) {
        ulonglong2 wv = wr2[kk];
        #pragma unroll
        for (int q = 0; q < 8; q++) {
            ulonglong2 iv = ((const ulonglong2*)(inp + q * 148))[kk];
            fma2(aX2[q], wv.x, iv.x);
            fma2(aX2[q], wv.y, iv.y);
        }
    }
    const ulonglong2* wh2 = (const ulonglong2*)(Whhc + g * 128);
    #pragma unroll 4
    for (int kk = 0; kk < 32; kk++) {
        ulonglong2 wv = wh2[kk];
        #pragma unroll
        for (int q = 0; q < 8; q++) {
            ulonglong2 hv = ((const ulonglong2*)(hprev + q * 128))[kk];
            fma2(aH2[q], wv.x, hv.x);
            fma2(aH2[q], wv.y, hv.y);
        }
    }
    float bi = bihc[g], bh = bhhc[g];
    #pragma unroll
    for (int q = 0; q < 8; q++) {
        float2 xv = unp2(aX2[q]), hv = unp2(aH2[q]);
        sX[g * 8 + q]  = bi + xv.x + xv.y;
        sH2[g * 8 + q] = bh + hv.x + hv.y;
    }
    __syncthreads();

    if (g < 128) {
        #pragma unroll
        for (int q = 0; q < 8; q++) {
            float r  = sigmoidf_(sX[g * 8 + q] + sH2[g * 8 + q]);
            float z  = sigmoidf_(sX[(g + 128) * 8 + q] + sH2[(g + 128) * 8 + q]);
            float nn = tanhf(sX[(g + 256) * 8 + q] + r * sH2[(g + 256) * 8 + q]);
            float hn = (1.f - z) * nn + z * hprev[q * 128 + g];
            g_h[(m0 + q) * DP + g] = hn;
            shn[q * 128 + g] = hn;
        }
    }
    __syncthreads();
    if (g < 128) {
        int q = g >> 4, c = g & 15;
        ull a2 = 0ull;
        const ulonglong2* rw2 = (const ulonglong2*)(readW + c * DP);
        const ulonglong2* hh2 = (const ulonglong2*)(shn + q * 128);
        #pragma unroll 8
        for (int kk = 0; kk < 32; kk++) {
            ulonglong2 wv = rw2[kk], hv = hh2[kk];
            fma2(a2, wv.x, hv.x);
            fma2(a2, wv.y, hv.y);
        }
        float2 av = unp2(a2);
        float yt = readb[c] + av.x + av.y + inp[q * 148 + 128 + c];
        int m = m0 + q;
        g_y[m * Cc + c] = yt;
        float yh = X[(m * Cc + c) * Tt + (Tt - 1)] + yt;
        out[(m * Cc + c) * TOUT + step] = yh;
        if (step == 0) out[BN * Cc * TOUT + m * Cc + c] = yh;
    }
}

extern "C" void kernel_launch(void* const* d_in, const int* in_sizes, int n_in,
                              void* d_out, int out_size) {
    const float* X      = (const float*)d_in[0];
    const int*   phases = (const int*)  d_in[1];
    const float* gWih   = (const float*)d_in[2];
    const float* gWhh   = (const float*)d_in[3];
    const float* gbih   = (const float*)d_in[4];
    const float* gbhh   = (const float*)d_in[5];
    const float* lng    = (const float*)d_in[6];
    const float* lnb    = (const float*)d_in[7];
    const float* tW     = (const float*)d_in[8];
    const float* tb     = (const float*)d_in[9];
    const float* S      = (const float*)d_in[10];
    const float* G      = (const float*)d_in[11];
    const float* Wself  = (const float*)d_in[12];
    const float* Wneigh = (const float*)d_in[13];
    const float* cWih   = (const float*)d_in[14];
    const float* cWhh   = (const float*)d_in[15];
    const float* cbih   = (const float*)d_in[16];
    const float* cbhh   = (const float*)d_in[17];
    const float* readW  = (const float*)d_in[18];
    const float* readb  = (const float*)d_in[19];
    const float* logtau = (const float*)d_in[22];
    float* out = (float*)d_out;

    cudaFuncSetAttribute(gru_kernel, cudaFuncAttributeMaxDynamicSharedMemorySize, GRU_SMEM);
    cudaFuncSetAttribute(feat_kernel, cudaFuncAttributeMaxDynamicSharedMemorySize, FEAT_SMEM);

    spec_kernel<<<1, 256>>>(Wneigh);
    prep_kernel<<<68, 256>>>(Wself, (const float*)d_in[20], (const float*)d_in[21]);
    graph_kernel<<<Bb, 256>>>(S, G, phases);
    gru_kernel<<<128, 384, GRU_SMEM>>>(X, gWih, gWhh, gbih, gbhh, lng, lnb);
    feat_kernel<<<Bb * 32, 512, FEAT_SMEM>>>(tW, tb);
    for (int s = 0; s < TOUT; s++) {
        attn_kernel<<<BN, 512>>>(logtau);
        cell_kernel<<<BN / 8, 384>>>(cWih, cWhh, cbih, cbhh, readW, readb, X, out, s);
    }
}

// round 15
// speedup vs baseline: 1.0327x; 1.0327x over previous
#include <cuda_runtime.h>
#include <cuda_bf16.h>
#include <math.h>

#define Bb 64
#define Nn 16
#define Cc 16
#define Tt 256
#define DH 128
#define DIN 136
#define DP 128
#define TOUT 32
#define BN 1024

typedef unsigned long long ull;

__device__ float g_Hc[BN * Tt * DH];           // [m][t][128]
__device__ __nv_bfloat16 g_Kh[BN * Tt * DP];   // [m][t][d] bf16
__device__ __nv_bfloat16 g_Vh[BN * Tt * DP];   // [m][t][d] bf16
__device__ float g_A [Bb * Nn * Nn];
__device__ float g_WnT[DIN * DP];
__device__ float g_WsT[DIN * DP];
__device__ float g_WkT[DP * DP];
__device__ float g_WvT[DP * DP];
__device__ float g_h  [BN * DP];
__device__ float g_y  [BN * Cc];
__device__ float g_ymix[BN * Cc];
__device__ float g_ctx [BN * DP];

// ---- f32x2 helpers ----
__device__ __forceinline__ ull dup2(float v) {
    ull r; asm("mov.b64 %0, {%1, %1};" : "=l"(r) : "f"(v)); return r;
}
__device__ __forceinline__ void fma2(ull& d, ull a, ull b) {
    asm("fma.rn.f32x2 %0, %1, %2, %0;" : "+l"(d) : "l"(a), "l"(b));
}
__device__ __forceinline__ float2 unp2(ull v) {
    float2 r; asm("mov.b64 {%0, %1}, %2;" : "=f"(r.x), "=f"(r.y) : "l"(v)); return r;
}
__device__ __forceinline__ unsigned bf2u(float a, float b) {
    __nv_bfloat162 h = __floats2bfloat162_rn(a, b);
    return *(unsigned*)&h;
}
__device__ __forceinline__ float2 bfu2f(unsigned u) {
    __nv_bfloat162 h = *(__nv_bfloat162*)&u;
    return __bfloat1622float2(h);
}

__device__ __forceinline__ float sigmoidf_(float x) { return 1.f / (1.f + expf(-x)); }
__device__ __forceinline__ float softplusf_(float x) {
    return x > 0.f ? x + log1pf(expf(-x)) : log1pf(expf(x));
}
__device__ __forceinline__ float block_sum256(float v, float* sbuf, int tid) {
    #pragma unroll
    for (int o = 16; o; o >>= 1) v += __shfl_xor_sync(0xffffffffu, v, o);
    if ((tid & 31) == 0) sbuf[tid >> 5] = v;
    __syncthreads();
    float r = 0.f;
    #pragma unroll
    for (int w = 0; w < 8; w++) r += sbuf[w];
    __syncthreads();
    return r;
}

// ---- spectral norm of W_neigh ----
__global__ void spec_kernel(const float* __restrict__ W) {
    __shared__ float su[DP], sv[DIN], sred[8];
    int tid = threadIdx.x;
    if (tid < DP) su[tid] = rsqrtf((float)DP);
    __syncthreads();
    for (int it = 0; it < 15; it++) {
        float vv = 0.f;
        if (tid < DIN)
            for (int i = 0; i < DP; i++) vv += W[i * DIN + tid] * su[i];
        float nv = sqrtf(block_sum256((tid < DIN) ? vv * vv : 0.f, sred, tid));
        if (tid < DIN) sv[tid] = vv / nv;
        __syncthreads();
        float uu = 0.f;
        if (tid < DP)
            for (int j = 0; j < DIN; j++) uu += W[tid * DIN + j] * sv[j];
        float nu = sqrtf(block_sum256((tid < DP) ? uu * uu : 0.f, sred, tid));
        if (tid < DP) su[tid] = uu / nu;
        __syncthreads();
    }
    float p = 0.f;
    if (tid < DP) {
        float t = 0.f;
        for (int j = 0; j < DIN; j++) t += W[tid * DIN + j] * sv[j];
        p = su[tid] * t;
    }
    float sigma = block_sum256(p, sred, tid);
    float inv = 1.f / sigma;
    for (int idx = tid; idx < DIN * DP; idx += 256) {
        int k = idx >> 7, d = idx & 127;
        g_WnT[idx] = W[d * DIN + k] * inv;
    }
}

__global__ void prep_kernel(const float* __restrict__ Ws, const float* __restrict__ Wk,
                            const float* __restrict__ Wv) {
    int idx = blockIdx.x * 256 + threadIdx.x;
    if (idx < DIN * DP) { int k = idx >> 7, d = idx & 127; g_WsT[idx] = Ws[d * DIN + k]; }
    if (idx < DP * DP)  { int k = idx >> 7, d = idx & 127; g_WkT[idx] = Wk[d * DP + k];
                          g_WvT[idx] = Wv[d * DP + k]; }
    if (idx < BN * Cc)  g_y[idx] = 0.f;
}

__global__ void graph_kernel(const float* __restrict__ S, const float* __restrict__ G,
                             const int* __restrict__ phases) {
    int b = blockIdx.x, tid = threadIdx.x;
    int i = tid >> 4, j = tid & 15;
    int p = phases[b];
    const float* Sp = S + p * 256;
    float denom = 0.f;
    #pragma unroll
    for (int jj = 0; jj < 16; jj++) if (jj != i) denom += fabsf(Sp[i * 16 + jj]);
    denom = fmaxf(denom, 1e-6f);
    float gsum = 0.f;
    #pragma unroll
    for (int ii = 0; ii < 16; ii++) gsum += softplusf_(G[p * 16 + ii]) + 1e-6f;
    gsum = fmaxf(gsum, 1e-6f);
    float gi = (softplusf_(G[p * 16 + i]) + 1e-6f) * (16.0f / gsum);
    float sz = (i == j) ? 0.f : Sp[i * 16 + j];
    g_A[b * 256 + tid] = sz / denom * gi;
}

// ---- GRU + LN: 8 sequences per block ----
#define QB 8
#define GRU_XQ   (Tt * 16)
#define GRU_SMEM ((QB * GRU_XQ + 384 * 20) * 4)

__global__ void __launch_bounds__(384, 1)
gru_kernel(const float* __restrict__ X, const float* __restrict__ Wih,
           const float* __restrict__ Whh, const float* __restrict__ bih,
           const float* __restrict__ bhh, const float* __restrict__ lng,
           const float* __restrict__ lnb) {
    extern __shared__ __align__(16) float dyn[];
    float* x_s   = dyn;
    float* wih_s = dyn + QB * GRU_XQ;
    __shared__ __align__(16) float h_s[QB][DH];
    __shared__ float sGx[QB][384];
    __shared__ float sGh[QB][384];
    __shared__ float spart[QB][8];

    int n = blockIdx.x & 15, bg = blockIdx.x >> 4;
    int g = threadIdx.x;

    for (int idx = g; idx < QB * Cc * Tt; idx += 384) {
        int q = idx >> 12, r = idx & 4095;
        int c = r >> 8, t = r & 255;
        int m = (bg * QB + q) * 16 + n;
        x_s[q * GRU_XQ + t * 16 + c] = X[m * (Cc * Tt) + r];
    }
    for (int idx = g; idx < 384 * 16; idx += 384) {
        int gg = idx >> 4, c = idx & 15;
        wih_s[gg * 20 + c] = Wih[n * 6144 + idx];
    }
    ull w2[64];
    {
        const ulonglong2* wp2 = (const ulonglong2*)(Whh + (n * 384 + g) * 128);
        #pragma unroll
        for (int k = 0; k < 32; k++) {
            ulonglong2 v = wp2[k];
            w2[2 * k] = v.x; w2[2 * k + 1] = v.y;
        }
    }
    float bi = bih[n * 384 + g], bh = bhh[n * 384 + g];
    float lg = 1.f, lbv = 0.f;
    if (g < 128) { lg = lng[g]; lbv = lnb[g]; }
    if (g < 128) {
        #pragma unroll
        for (int q = 0; q < QB; q++) h_s[q][g] = 0.f;
    }
    __syncthreads();

    for (int t = 0; t < Tt; t++) {
        #pragma unroll
        for (int q = 0; q < QB; q++) {
            ull hA = 0, hB = 0;
            const ulonglong2* h2 = (const ulonglong2*)h_s[q];
            #pragma unroll
            for (int k = 0; k < 32; k++) {
                ulonglong2 hv = h2[k];
                fma2(hA, w2[2 * k],     hv.x);
                fma2(hB, w2[2 * k + 1], hv.y);
            }
            ull axA = 0, axB = 0;
            const ulonglong2* xr = (const ulonglong2*)(x_s + q * GRU_XQ + t * 16);
            const ulonglong2* wi = (const ulonglong2*)(wih_s + g * 20);
            #pragma unroll
            for (int k = 0; k < 4; k++) {
                ulonglong2 wv = wi[k], xv = xr[k];
                fma2(axA, wv.x, xv.x);
                fma2(axB, wv.y, xv.y);
            }
            float2 fa = unp2(hA), fb = unp2(hB);
            float2 xa = unp2(axA), xb = unp2(axB);
            sGh[q][g] = bh + ((fa.x + fa.y) + (fb.x + fb.y));
            sGx[q][g] = bi + ((xa.x + xa.y) + (xb.x + xb.y));
        }
        __syncthreads();
        float hn[QB];
        if (g < 128) {
            float s1[QB], s2[QB];
            #pragma unroll
            for (int q = 0; q < QB; q++) {
                float r  = sigmoidf_(sGx[q][g] + sGh[q][g]);
                float z  = sigmoidf_(sGx[q][g + 128] + sGh[q][g + 128]);
                float nn = tanhf(sGx[q][g + 256] + r * sGh[q][g + 256]);
                float h0 = h_s[q][g];
                hn[q] = (1.f - z) * nn + z * h0;
                h_s[q][g] = hn[q];
                s1[q] = hn[q]; s2[q] = hn[q] * hn[q];
            }
            #pragma unroll
            for (int o = 16; o; o >>= 1) {
                #pragma unroll
                for (int q = 0; q < QB; q++) {
                    s1[q] += __shfl_down_sync(0xffffffffu, s1[q], o);
                    s2[q] += __shfl_down_sync(0xffffffffu, s2[q], o);
                }
            }
            if ((g & 31) == 0) {
                int wid = g >> 5;
                #pragma unroll
                for (int q = 0; q < QB; q++) {
                    spart[q][wid] = s1[q]; spart[q][4 + wid] = s2[q];
                }
            }
        }
        __syncthreads();
        if (g < 128) {
            #pragma unroll
            for (int q = 0; q < QB; q++) {
                float m1 = (spart[q][0]+spart[q][1]+spart[q][2]+spart[q][3]) * (1.f/128.f);
                float m2 = (spart[q][4]+spart[q][5]+spart[q][6]+spart[q][7]) * (1.f/128.f) - m1*m1;
                float inv = rsqrtf(m2 + 1e-5f);
                int m = (bg * QB + q) * 16 + n;
                g_Hc[(m * Tt + t) * DH + g] = (hn[q] - m1) * inv * lg + lbv;
            }
        }
    }
}

// ---- fused feature stage (256 thr, 8x8 tile) ----
__device__ __forceinline__ void zeroacc(ull acc2[8][4]) {
    #pragma unroll
    for (int r = 0; r < 8; r++) {
        #pragma unroll
        for (int c = 0; c < 4; c++) acc2[r][c] = 0ull;
    }
}

__device__ __forceinline__ void gemmf2(ull acc2[8][4], const float* sA, int lda,
                                       const float* sB, int kd, int R0, int C0) {
    #pragma unroll 2
    for (int k = 0; k < kd; k++) {
        ulonglong2 bA = *(const ulonglong2*)(sB + k * 128 + C0);
        ulonglong2 bB = *(const ulonglong2*)(sB + k * 128 + C0 + 4);
        #pragma unroll
        for (int r = 0; r < 8; r++) {
            ull a2 = dup2(sA[(R0 + r) * lda + k]);
            fma2(acc2[r][0], a2, bA.x);
            fma2(acc2[r][1], a2, bA.y);
            fma2(acc2[r][2], a2, bB.x);
            fma2(acc2[r][3], a2, bB.y);
        }
    }
}

#define SH_LD 137
#define SZ_LD 136
#define SP_LD 132
#define FEAT_SMEM ((128*SH_LD + DIN*128 + 128*SP_LD + 256) * 4)

__global__ void __launch_bounds__(256, 1) feat_kernel(const float* __restrict__ tW,
                                                      const float* __restrict__ tb) {
    extern __shared__ float sm[];
    float* sH   = sm;
    float* sW   = sm + 128 * SH_LD;
    float* sP   = sW + DIN * 128;
    float* sA16 = sP + 128 * SP_LD;

    int b = blockIdx.x >> 5, tt = blockIdx.x & 31;
    int tid = threadIdx.x, tx = tid & 15, ty = tid >> 4;
    int R0 = ty * 8, C0 = tx * 8;

    for (int idx = tid; idx < 128 * DIN; idx += 256) {
        int r = idx / DIN, c = idx - r * DIN;
        int n = r >> 3, tl = r & 7;
        float v;
        if (c < 128) {
            v = g_Hc[((b * 16 + n) * Tt + tt * 8 + tl) * DH + c];
        } else {
            float tv = (float)(tt * 8 + tl) * (1.f / 255.f);
            v = tanhf(tv * tW[c - 128] + tb[c - 128]);
        }
        sH[r * SH_LD + c] = v;
    }
    for (int idx = tid; idx < DIN * 128; idx += 256) sW[idx] = g_WnT[idx];
    sA16[tid] = g_A[b * 256 + tid];
    __syncthreads();

    ull acc2[8][4];
    zeroacc(acc2);
    gemmf2(acc2, sH, SH_LD, sW, DIN, R0, C0);
    __syncthreads();
    #pragma unroll
    for (int r = 0; r < 8; r++) {
        *(ulonglong2*)&sP[(R0+r)*SP_LD + C0]     = make_ulonglong2(acc2[r][0], acc2[r][1]);
        *(ulonglong2*)&sP[(R0+r)*SP_LD + C0 + 4] = make_ulonglong2(acc2[r][2], acc2[r][3]);
    }
    for (int idx = tid; idx < DIN * 128; idx += 256) sW[idx] = g_WsT[idx];
    __syncthreads();

    zeroacc(acc2);
    gemmf2(acc2, sH, SH_LD, sW, DIN, R0, C0);
    {
        #pragma unroll
        for (int j = 0; j < 16; j++) {
            ull a2 = dup2(sA16[ty * 16 + j]);
            #pragma unroll
            for (int r = 0; r < 8; r++) {
                const float* pr = &sP[(j * 8 + r) * SP_LD + C0];
                ulonglong2 p0 = *(const ulonglong2*)pr;
                ulonglong2 p1 = *(const ulonglong2*)(pr + 4);
                fma2(acc2[r][0], a2, p0.x);
                fma2(acc2[r][1], a2, p0.y);
                fma2(acc2[r][2], a2, p1.x);
                fma2(acc2[r][3], a2, p1.y);
            }
        }
    }
    float accf[8][8];
    #pragma unroll
    for (int r = 0; r < 8; r++) {
        #pragma unroll
        for (int p = 0; p < 4; p++) {
            float2 v = unp2(acc2[r][p]);
            accf[r][2*p]   = v.x >= 0.f ? v.x : 0.1f * v.x;
            accf[r][2*p+1] = v.y >= 0.f ? v.y : 0.1f * v.y;
        }
    }
    __syncthreads();
    #pragma unroll
    for (int r = 0; r < 8; r++) {
        int row = R0 + r;
        *(float4*)&sH[row*SZ_LD + C0]     = make_float4(accf[r][0],accf[r][1],accf[r][2],accf[r][3]);
        *(float4*)&sH[row*SZ_LD + C0 + 4] = make_float4(accf[r][4],accf[r][5],accf[r][6],accf[r][7]);
        if (tt == 31 && r == 7) {
            float* hp = g_h + (b * 16 + ty) * DP + C0;
            #pragma unroll
            for (int c = 0; c < 8; c++) hp[c] = accf[r][c];
        }
    }
    for (int idx = tid; idx < DP * DP; idx += 256) sW[idx] = g_WkT[idx];
    __syncthreads();

    zeroacc(acc2);
    gemmf2(acc2, sH, SZ_LD, sW, DP, R0, C0);
    #pragma unroll
    for (int r = 0; r < 8; r++) {
        int mm = b * 16 + ty;
        int tg = tt * 8 + r;
        float2 v0 = unp2(acc2[r][0]), v1 = unp2(acc2[r][1]);
        float2 v2 = unp2(acc2[r][2]), v3 = unp2(acc2[r][3]);
        uint4 o;
        o.x = bf2u(v0.x, v0.y);
        o.y = bf2u(v1.x, v1.y);
        o.z = bf2u(v2.x, v2.y);
        o.w = bf2u(v3.x, v3.y);
        *(uint4*)&g_Kh[(mm * Tt + tg) * DP + C0] = o;
    }
    __syncthreads();
    for (int idx = tid; idx < DP * DP; idx += 256) sW[idx] = g_WvT[idx];
    __syncthreads();

    zeroacc(acc2);
    gemmf2(acc2, sH, SZ_LD, sW, DP, R0, C0);
    #pragma unroll
    for (int r = 0; r < 8; r++) {
        int mm = b * 16 + ty;
        int tg = tt * 8 + r;
        float2 v0 = unp2(acc2[r][0]), v1 = unp2(acc2[r][1]);
        float2 v2 = unp2(acc2[r][2]), v3 = unp2(acc2[r][3]);
        uint4 o;
        o.x = bf2u(v0.x, v0.y);
        o.y = bf2u(v1.x, v1.y);
        o.z = bf2u(v2.x, v2.y);
        o.w = bf2u(v3.x, v3.y);
        *(uint4*)&g_Vh[(mm * Tt + tg) * DP + C0] = o;
    }
}

// ---- decoder: attention (coalesced warp-row scores, pre-scaled h) ----
__global__ void __launch_bounds__(512) attn_kernel(const float* __restrict__ log_tau) {
    __shared__ __align__(16) float h_s[DP];
    __shared__ float al[Tt];
    __shared__ float sc[Tt];
    __shared__ float red[8], red2[8];
    __shared__ __align__(16) float part[32][132];
    int m = blockIdx.x, tid = threadIdx.x;
    int w = tid >> 5, lane = tid & 31;
    float scale = expf(log_tau[0]);
    if (tid < DP) h_s[tid] = g_h[m * DP + tid] * scale;
    if (tid >= 256 && tid < 272) {
        int c = tid - 256, b = m >> 4, i = m & 15;
        float s = 0.f;
        #pragma unroll
        for (int j = 0; j < 16; j++) s += g_A[b * 256 + i * 16 + j] * g_y[(b * 16 + j) * Cc + c];
        g_ymix[m * Cc + c] = g_y[m * Cc + c] + 0.3f * s;
    }
    __syncthreads();
    {
        float h0 = h_s[lane * 4], h1 = h_s[lane * 4 + 1];
        float h2 = h_s[lane * 4 + 2], h3 = h_s[lane * 4 + 3];
        #pragma unroll 4
        for (int r = 0; r < 16; r++) {
            int t = w * 16 + r;
            uint2 kv = *(const uint2*)(g_Kh + (m * Tt + t) * DP + lane * 4);
            float2 a0 = bfu2f(kv.x), a1 = bfu2f(kv.y);
            float dot = a0.x * h0 + a0.y * h1 + a1.x * h2 + a1.y * h3;
            #pragma unroll
            for (int o = 16; o; o >>= 1) dot += __shfl_xor_sync(0xffffffffu, dot, o);
            if (lane == 0) sc[t] = dot;
        }
    }
    __syncthreads();
    if (tid < 256) {
        float sv = sc[tid];
        float mx = sv;
        #pragma unroll
        for (int o = 16; o; o >>= 1) mx = fmaxf(mx, __shfl_xor_sync(0xffffffffu, mx, o));
        if ((tid & 31) == 0) red[tid >> 5] = mx;
    }
    __syncthreads();
    if (tid < 256) {
        float bmx = red[0];
        #pragma unroll
        for (int w2 = 1; w2 < 8; w2++) bmx = fmaxf(bmx, red[w2]);
        float ev = expf(sc[tid] - bmx);
        al[tid] = ev;
        float ss = ev;
        #pragma unroll
        for (int o = 16; o; o >>= 1) ss += __shfl_xor_sync(0xffffffffu, ss, o);
        if ((tid & 31) == 0) red2[tid >> 5] = ss;
    }
    __syncthreads();
    float tot = 0.f;
    #pragma unroll
    for (int w2 = 0; w2 < 8; w2++) tot += red2[w2];
    float inv = 1.f / tot;
    {
        int dsl = tid & 15, tch = tid >> 4;
        float acc[8];
        #pragma unroll
        for (int j = 0; j < 8; j++) acc[j] = 0.f;
        #pragma unroll
        for (int u = 0; u < 8; u++) {
            int t2 = tch * 8 + u;
            uint4 v = *(const uint4*)(g_Vh + (m * Tt + t2) * DP + dsl * 8);
            float a = al[t2];
            float2 f0 = bfu2f(v.x), f1 = bfu2f(v.y), f2 = bfu2f(v.z), f3 = bfu2f(v.w);
            acc[0] += a * f0.x; acc[1] += a * f0.y;
            acc[2] += a * f1.x; acc[3] += a * f1.y;
            acc[4] += a * f2.x; acc[5] += a * f2.y;
            acc[6] += a * f3.x; acc[7] += a * f3.y;
        }
        *(float4*)&part[tch][dsl * 8]     = make_float4(acc[0], acc[1], acc[2], acc[3]);
        *(float4*)&part[tch][dsl * 8 + 4] = make_float4(acc[4], acc[5], acc[6], acc[7]);
    }
    __syncthreads();
    if (tid < 128) {
        float c = 0.f;
        #pragma unroll
        for (int ch = 0; ch < 32; ch++) c += part[ch][tid];
        g_ctx[m * DP + tid] = c * inv;
    }
}

// ---- decoder: GRU cell + readout (f32x2) ----
__global__ void __launch_bounds__(384) cell_kernel(const float* __restrict__ Wihc,
                                                   const float* __restrict__ Whhc,
                                                   const float* __restrict__ bihc,
                                                   const float* __restrict__ bhhc,
                                                   const float* __restrict__ readW,
                                                   const float* __restrict__ readb,
                                                   const float* __restrict__ X,
                                                   float* __restrict__ out, int step) {
    __shared__ __align__(16) float inp[8 * 148];
    __shared__ __align__(16) float hprev[8 * 128];
    __shared__ float sX[384 * 8], sH2[384 * 8];
    __shared__ float shn[8 * 128];
    int m0 = blockIdx.x * 8, g = threadIdx.x;

    for (int idx = g; idx < 8 * 128; idx += 384) {
        int q = idx >> 7, d = idx & 127;
        inp[q * 148 + d] = g_ctx[(m0 + q) * DP + d];
        hprev[idx] = g_h[(m0 + q) * DP + d];
    }
    for (int idx = g; idx < 8 * 16; idx += 384) {
        int q = idx >> 4, c = idx & 15;
        inp[q * 148 + 128 + c] = g_ymix[(m0 + q) * Cc + c];
    }
    __syncthreads();

    ull aX2[8], aH2[8];
    #pragma unroll
    for (int q = 0; q < 8; q++) { aX2[q] = 0ull; aH2[q] = 0ull; }
    const ulonglong2* wr2 = (const ulonglong2*)(Wihc + g * 144);
    #pragma unroll 4
    for (int kk = 0; kk < 36; kk++) {
        ulonglong2 wv = wr2[kk];
        #pragma unroll
        for (int q = 0; q < 8; q++) {
            ulonglong2 iv = ((const ulonglong2*)(inp + q * 148))[kk];
            fma2(aX2[q], wv.x, iv.x);
            fma2(aX2[q], wv.y, iv.y);
        }
    }
    const ulonglong2* wh2 = (const ulonglong2*)(Whhc + g * 128);
    #pragma unroll 4
    for (int kk = 0; kk < 32; kk++) {
        ulonglong2 wv = wh2[kk];
        #pragma unroll
        for (int q = 0; q < 8; q++) {
            ulonglong2 hv = ((const ulonglong2*)(hprev + q * 128))[kk];
            fma2(aH2[q], wv.x, hv.x);
            fma2(aH2[q], wv.y, hv.y);
        }
    }
    float bi = bihc[g], bh = bhhc[g];
    #pragma unroll
    for (int q = 0; q < 8; q++) {
        float2 xv = unp2(aX2[q]), hv = unp2(aH2[q]);
        sX[g * 8 + q]  = bi + xv.x + xv.y;
        sH2[g * 8 + q] = bh + hv.x + hv.y;
    }
    __syncthreads();

    if (g < 128) {
        #pragma unroll
        for (int q = 0; q < 8; q++) {
            float r  = sigmoidf_(sX[g * 8 + q] + sH2[g * 8 + q]);
            float z  = sigmoidf_(sX[(g + 128) * 8 + q] + sH2[(g + 128) * 8 + q]);
            float nn = tanhf(sX[(g + 256) * 8 + q] + r * sH2[(g + 256) * 8 + q]);
            float hn = (1.f - z) * nn + z * hprev[q * 128 + g];
            g_h[(m0 + q) * DP + g] = hn;
            shn[q * 128 + g] = hn;
        }
    }
    __syncthreads();
    if (g < 128) {
        int q = g >> 4, c = g & 15;
        ull a2 = 0ull;
        const ulonglong2* rw2 = (const ulonglong2*)(readW + c * DP);
        const ulonglong2* hh2 = (const ulonglong2*)(shn + q * 128);
        #pragma unroll 8
        for (int kk = 0; kk < 32; kk++) {
            ulonglong2 wv = rw2[kk], hv = hh2[kk];
            fma2(a2, wv.x, hv.x);
            fma2(a2, wv.y, hv.y);
        }
        float2 av = unp2(a2);
        float yt = readb[c] + av.x + av.y + inp[q * 148 + 128 + c];
        int m = m0 + q;
        g_y[m * Cc + c] = yt;
        float yh = X[(m * Cc + c) * Tt + (Tt - 1)] + yt;
        out[(m * Cc + c) * TOUT + step] = yh;
        if (step == 0) out[BN * Cc * TOUT + m * Cc + c] = yh;
    }
}

extern "C" void kernel_launch(void* const* d_in, const int* in_sizes, int n_in,
                              void* d_out, int out_size) {
    const float* X      = (const float*)d_in[0];
    const int*   phases = (const int*)  d_in[1];
    const float* gWih   = (const float*)d_in[2];
    const float* gWhh   = (const float*)d_in[3];
    const float* gbih   = (const float*)d_in[4];
    const float* gbhh   = (const float*)d_in[5];
    const float* lng    = (const float*)d_in[6];
    const float* lnb    = (const float*)d_in[7];
    const float* tW     = (const float*)d_in[8];
    const float* tb     = (const float*)d_in[9];
    const float* S      = (const float*)d_in[10];
    const float* G      = (const float*)d_in[11];
    const float* Wself  = (const float*)d_in[12];
    const float* Wneigh = (const float*)d_in[13];
    const float* cWih   = (const float*)d_in[14];
    const float* cWhh   = (const float*)d_in[15];
    const float* cbih   = (const float*)d_in[16];
    const float* cbhh   = (const float*)d_in[17];
    const float* readW  = (const float*)d_in[18];
    const float* readb  = (const float*)d_in[19];
    const float* logtau = (const float*)d_in[22];
    float* out = (float*)d_out;

    cudaFuncSetAttribute(gru_kernel, cudaFuncAttributeMaxDynamicSharedMemorySize, GRU_SMEM);
    cudaFuncSetAttribute(feat_kernel, cudaFuncAttributeMaxDynamicSharedMemorySize, FEAT_SMEM);

    spec_kernel<<<1, 256>>>(Wneigh);
    prep_kernel<<<68, 256>>>(Wself, (const float*)d_in[20], (const float*)d_in[21]);
    graph_kernel<<<Bb, 256>>>(S, G, phases);
    gru_kernel<<<128, 384, GRU_SMEM>>>(X, gWih, gWhh, gbih, gbhh, lng, lnb);
    feat_kernel<<<Bb * 32, 256, FEAT_SMEM>>>(tW, tb);
    for (int s = 0; s < TOUT; s++) {
        attn_kernel<<<BN, 512>>>(logtau);
        cell_kernel<<<BN / 8, 384>>>(cWih, cWhh, cbih, cbhh, readW, readb, X, out, s);
    }
}

// round 16
// speedup vs baseline: 1.0572x; 1.0238x over previous
#include <cuda_runtime.h>
#include <cuda_bf16.h>
#include <math.h>

#define Bb 64
#define Nn 16
#define Cc 16
#define Tt 256
#define DH 128
#define DIN 136
#define DP 128
#define TOUT 32
#define BN 1024

typedef unsigned long long ull;

__device__ float g_Hc[BN * Tt * DH];
__device__ __nv_bfloat16 g_Kh[BN * Tt * DP];
__device__ __nv_bfloat16 g_Vh[BN * Tt * DP];
__device__ float g_A [Bb * Nn * Nn];
__device__ float g_WnT[DIN * DP];
__device__ float g_WsT[DIN * DP];
__device__ float g_WkT[DP * DP];
__device__ float g_WvT[DP * DP];
__device__ float g_h  [BN * DP];
__device__ float g_y  [BN * Cc];
__device__ float g_ymix[BN * Cc];
__device__ float g_ctx [BN * DP];

__device__ __forceinline__ ull dup2(float v) {
    ull r; asm("mov.b64 %0, {%1, %1};" : "=l"(r) : "f"(v)); return r;
}
__device__ __forceinline__ void fma2(ull& d, ull a, ull b) {
    asm("fma.rn.f32x2 %0, %1, %2, %0;" : "+l"(d) : "l"(a), "l"(b));
}
__device__ __forceinline__ float2 unp2(ull v) {
    float2 r; asm("mov.b64 {%0, %1}, %2;" : "=f"(r.x), "=f"(r.y) : "l"(v)); return r;
}
__device__ __forceinline__ unsigned bf2u(float a, float b) {
    __nv_bfloat162 h = __floats2bfloat162_rn(a, b);
    return *(unsigned*)&h;
}
__device__ __forceinline__ float2 bfu2f(unsigned u) {
    __nv_bfloat162 h = *(__nv_bfloat162*)&u;
    return __bfloat1622float2(h);
}

__device__ __forceinline__ float sigmoidf_(float x) { return 1.f / (1.f + expf(-x)); }
__device__ __forceinline__ float softplusf_(float x) {
    return x > 0.f ? x + log1pf(expf(-x)) : log1pf(expf(x));
}
__device__ __forceinline__ float block_sum256(float v, float* sbuf, int tid) {
    #pragma unroll
    for (int o = 16; o; o >>= 1) v += __shfl_xor_sync(0xffffffffu, v, o);
    if ((tid & 31) == 0) sbuf[tid >> 5] = v;
    __syncthreads();
    float r = 0.f;
    #pragma unroll
    for (int w = 0; w < 8; w++) r += sbuf[w];
    __syncthreads();
    return r;
}

__global__ void spec_kernel(const float* __restrict__ W) {
    __shared__ float su[DP], sv[DIN], sred[8];
    int tid = threadIdx.x;
    if (tid < DP) su[tid] = rsqrtf((float)DP);
    __syncthreads();
    for (int it = 0; it < 15; it++) {
        float vv = 0.f;
        if (tid < DIN)
            for (int i = 0; i < DP; i++) vv += W[i * DIN + tid] * su[i];
        float nv = sqrtf(block_sum256((tid < DIN) ? vv * vv : 0.f, sred, tid));
        if (tid < DIN) sv[tid] = vv / nv;
        __syncthreads();
        float uu = 0.f;
        if (tid < DP)
            for (int j = 0; j < DIN; j++) uu += W[tid * DIN + j] * sv[j];
        float nu = sqrtf(block_sum256((tid < DP) ? uu * uu : 0.f, sred, tid));
        if (tid < DP) su[tid] = uu / nu;
        __syncthreads();
    }
    float p = 0.f;
    if (tid < DP) {
        float t = 0.f;
        for (int j = 0; j < DIN; j++) t += W[tid * DIN + j] * sv[j];
        p = su[tid] * t;
    }
    float sigma = block_sum256(p, sred, tid);
    float inv = 1.f / sigma;
    for (int idx = tid; idx < DIN * DP; idx += 256) {
        int k = idx >> 7, d = idx & 127;
        g_WnT[idx] = W[d * DIN + k] * inv;
    }
}

__global__ void prep_kernel(const float* __restrict__ Ws, const float* __restrict__ Wk,
                            const float* __restrict__ Wv) {
    int idx = blockIdx.x * 256 + threadIdx.x;
    if (idx < DIN * DP) { int k = idx >> 7, d = idx & 127; g_WsT[idx] = Ws[d * DIN + k]; }
    if (idx < DP * DP)  { int k = idx >> 7, d = idx & 127; g_WkT[idx] = Wk[d * DP + k];
                          g_WvT[idx] = Wv[d * DP + k]; }
    if (idx < BN * Cc)  g_y[idx] = 0.f;
}

__global__ void graph_kernel(const float* __restrict__ S, const float* __restrict__ G,
                             const int* __restrict__ phases) {
    int b = blockIdx.x, tid = threadIdx.x;
    int i = tid >> 4, j = tid & 15;
    int p = phases[b];
    const float* Sp = S + p * 256;
    float denom = 0.f;
    #pragma unroll
    for (int jj = 0; jj < 16; jj++) if (jj != i) denom += fabsf(Sp[i * 16 + jj]);
    denom = fmaxf(denom, 1e-6f);
    float gsum = 0.f;
    #pragma unroll
    for (int ii = 0; ii < 16; ii++) gsum += softplusf_(G[p * 16 + ii]) + 1e-6f;
    gsum = fmaxf(gsum, 1e-6f);
    float gi = (softplusf_(G[p * 16 + i]) + 1e-6f) * (16.0f / gsum);
    float sz = (i == j) ? 0.f : Sp[i * 16 + j];
    g_A[b * 256 + tid] = sz / denom * gi;
}

// ---- GRU + LN: 8 sequences per block, 4 fma2 chains ----
#define QB 8
#define GRU_XQ   (Tt * 16)
#define GRU_SMEM ((QB * GRU_XQ + 384 * 20) * 4)

__global__ void __launch_bounds__(384, 1)
gru_kernel(const float* __restrict__ X, const float* __restrict__ Wih,
           const float* __restrict__ Whh, const float* __restrict__ bih,
           const float* __restrict__ bhh, const float* __restrict__ lng,
           const float* __restrict__ lnb) {
    extern __shared__ __align__(16) float dyn[];
    float* x_s   = dyn;
    float* wih_s = dyn + QB * GRU_XQ;
    __shared__ __align__(16) float h_s[QB][DH];
    __shared__ float sGx[QB][384];
    __shared__ float sGh[QB][384];
    __shared__ float spart[QB][8];

    int n = blockIdx.x & 15, bg = blockIdx.x >> 4;
    int g = threadIdx.x;

    for (int idx = g; idx < QB * Cc * Tt; idx += 384) {
        int q = idx >> 12, r = idx & 4095;
        int c = r >> 8, t = r & 255;
        int m = (bg * QB + q) * 16 + n;
        x_s[q * GRU_XQ + t * 16 + c] = X[m * (Cc * Tt) + r];
    }
    for (int idx = g; idx < 384 * 16; idx += 384) {
        int gg = idx >> 4, c = idx & 15;
        wih_s[gg * 20 + c] = Wih[n * 6144 + idx];
    }
    ull w2[64];
    {
        const ulonglong2* wp2 = (const ulonglong2*)(Whh + (n * 384 + g) * 128);
        #pragma unroll
        for (int k = 0; k < 32; k++) {
            ulonglong2 v = wp2[k];
            w2[2 * k] = v.x; w2[2 * k + 1] = v.y;
        }
    }
    float bi = bih[n * 384 + g], bh = bhh[n * 384 + g];
    float lg = 1.f, lbv = 0.f;
    if (g < 128) { lg = lng[g]; lbv = lnb[g]; }
    if (g < 128) {
        #pragma unroll
        for (int q = 0; q < QB; q++) h_s[q][g] = 0.f;
    }
    __syncthreads();

    for (int t = 0; t < Tt; t++) {
        #pragma unroll
        for (int q = 0; q < QB; q++) {
            ull hA = 0, hB = 0, hC = 0, hD = 0;
            const ulonglong2* h2 = (const ulonglong2*)h_s[q];
            #pragma unroll
            for (int k = 0; k < 16; k++) {
                ulonglong2 hv0 = h2[2 * k];
                ulonglong2 hv1 = h2[2 * k + 1];
                fma2(hA, w2[4 * k],     hv0.x);
                fma2(hB, w2[4 * k + 1], hv0.y);
                fma2(hC, w2[4 * k + 2], hv1.x);
                fma2(hD, w2[4 * k + 3], hv1.y);
            }
            ull axA = 0, axB = 0;
            const ulonglong2* xr = (const ulonglong2*)(x_s + q * GRU_XQ + t * 16);
            const ulonglong2* wi = (const ulonglong2*)(wih_s + g * 20);
            #pragma unroll
            for (int k = 0; k < 4; k++) {
                ulonglong2 wv = wi[k], xv = xr[k];
                fma2(axA, wv.x, xv.x);
                fma2(axB, wv.y, xv.y);
            }
            float2 fa = unp2(hA), fb = unp2(hB), fc = unp2(hC), fd = unp2(hD);
            float2 xa = unp2(axA), xb = unp2(axB);
            sGh[q][g] = bh + (((fa.x + fa.y) + (fb.x + fb.y)) + ((fc.x + fc.y) + (fd.x + fd.y)));
            sGx[q][g] = bi + ((xa.x + xa.y) + (xb.x + xb.y));
        }
        __syncthreads();
        float hn[QB];
        if (g < 128) {
            float s1[QB], s2[QB];
            #pragma unroll
            for (int q = 0; q < QB; q++) {
                float r  = sigmoidf_(sGx[q][g] + sGh[q][g]);
                float z  = sigmoidf_(sGx[q][g + 128] + sGh[q][g + 128]);
                float nn = tanhf(sGx[q][g + 256] + r * sGh[q][g + 256]);
                float h0 = h_s[q][g];
                hn[q] = (1.f - z) * nn + z * h0;
                h_s[q][g] = hn[q];
                s1[q] = hn[q]; s2[q] = hn[q] * hn[q];
            }
            #pragma unroll
            for (int o = 16; o; o >>= 1) {
                #pragma unroll
                for (int q = 0; q < QB; q++) {
                    s1[q] += __shfl_down_sync(0xffffffffu, s1[q], o);
                    s2[q] += __shfl_down_sync(0xffffffffu, s2[q], o);
                }
            }
            if ((g & 31) == 0) {
                int wid = g >> 5;
                #pragma unroll
                for (int q = 0; q < QB; q++) {
                    spart[q][wid] = s1[q]; spart[q][4 + wid] = s2[q];
                }
            }
        }
        __syncthreads();
        if (g < 128) {
            #pragma unroll
            for (int q = 0; q < QB; q++) {
                float m1 = (spart[q][0]+spart[q][1]+spart[q][2]+spart[q][3]) * (1.f/128.f);
                float m2 = (spart[q][4]+spart[q][5]+spart[q][6]+spart[q][7]) * (1.f/128.f) - m1*m1;
                float inv = rsqrtf(m2 + 1e-5f);
                int m = (bg * QB + q) * 16 + n;
                g_Hc[(m * Tt + t) * DH + g] = (hn[q] - m1) * inv * lg + lbv;
            }
        }
    }
}

// ---- fused feature stage (256 thr, 8x8 tile) ----
__device__ __forceinline__ void zeroacc(ull acc2[8][4]) {
    #pragma unroll
    for (int r = 0; r < 8; r++) {
        #pragma unroll
        for (int c = 0; c < 4; c++) acc2[r][c] = 0ull;
    }
}

__device__ __forceinline__ void gemmf2(ull acc2[8][4], const float* sA, int lda,
                                       const float* sB, int kd, int R0, int C0) {
    #pragma unroll 2
    for (int k = 0; k < kd; k++) {
        ulonglong2 bA = *(const ulonglong2*)(sB + k * 128 + C0);
        ulonglong2 bB = *(const ulonglong2*)(sB + k * 128 + C0 + 4);
        #pragma unroll
        for (int r = 0; r < 8; r++) {
            ull a2 = dup2(sA[(R0 + r) * lda + k]);
            fma2(acc2[r][0], a2, bA.x);
            fma2(acc2[r][1], a2, bA.y);
            fma2(acc2[r][2], a2, bB.x);
            fma2(acc2[r][3], a2, bB.y);
        }
    }
}

#define SH_LD 137
#define SZ_LD 136
#define SP_LD 132
#define FEAT_SMEM ((128*SH_LD + DIN*128 + 128*SP_LD + 256) * 4)

__global__ void __launch_bounds__(256, 1) feat_kernel(const float* __restrict__ tW,
                                                      const float* __restrict__ tb) {
    extern __shared__ float sm[];
    float* sH   = sm;
    float* sW   = sm + 128 * SH_LD;
    float* sP   = sW + DIN * 128;
    float* sA16 = sP + 128 * SP_LD;

    int b = blockIdx.x >> 5, tt = blockIdx.x & 31;
    int tid = threadIdx.x, tx = tid & 15, ty = tid >> 4;
    int R0 = ty * 8, C0 = tx * 8;

    for (int idx = tid; idx < 128 * DIN; idx += 256) {
        int r = idx / DIN, c = idx - r * DIN;
        int n = r >> 3, tl = r & 7;
        float v;
        if (c < 128) {
            v = g_Hc[((b * 16 + n) * Tt + tt * 8 + tl) * DH + c];
        } else {
            float tv = (float)(tt * 8 + tl) * (1.f / 255.f);
            v = tanhf(tv * tW[c - 128] + tb[c - 128]);
        }
        sH[r * SH_LD + c] = v;
    }
    for (int idx = tid; idx < DIN * 128; idx += 256) sW[idx] = g_WnT[idx];
    sA16[tid] = g_A[b * 256 + tid];
    __syncthreads();

    ull acc2[8][4];
    zeroacc(acc2);
    gemmf2(acc2, sH, SH_LD, sW, DIN, R0, C0);
    __syncthreads();
    #pragma unroll
    for (int r = 0; r < 8; r++) {
        *(ulonglong2*)&sP[(R0+r)*SP_LD + C0]     = make_ulonglong2(acc2[r][0], acc2[r][1]);
        *(ulonglong2*)&sP[(R0+r)*SP_LD + C0 + 4] = make_ulonglong2(acc2[r][2], acc2[r][3]);
    }
    for (int idx = tid; idx < DIN * 128; idx += 256) sW[idx] = g_WsT[idx];
    __syncthreads();

    zeroacc(acc2);
    gemmf2(acc2, sH, SH_LD, sW, DIN, R0, C0);
    {
        #pragma unroll
        for (int j = 0; j < 16; j++) {
            ull a2 = dup2(sA16[ty * 16 + j]);
            #pragma unroll
            for (int r = 0; r < 8; r++) {
                const float* pr = &sP[(j * 8 + r) * SP_LD + C0];
                ulonglong2 p0 = *(const ulonglong2*)pr;
                ulonglong2 p1 = *(const ulonglong2*)(pr + 4);
                fma2(acc2[r][0], a2, p0.x);
                fma2(acc2[r][1], a2, p0.y);
                fma2(acc2[r][2], a2, p1.x);
                fma2(acc2[r][3], a2, p1.y);
            }
        }
    }
    float accf[8][8];
    #pragma unroll
    for (int r = 0; r < 8; r++) {
        #pragma unroll
        for (int p = 0; p < 4; p++) {
            float2 v = unp2(acc2[r][p]);
            accf[r][2*p]   = v.x >= 0.f ? v.x : 0.1f * v.x;
            accf[r][2*p+1] = v.y >= 0.f ? v.y : 0.1f * v.y;
        }
    }
    __syncthreads();
    #pragma unroll
    for (int r = 0; r < 8; r++) {
        int row = R0 + r;
        *(float4*)&sH[row*SZ_LD + C0]     = make_float4(accf[r][0],accf[r][1],accf[r][2],accf[r][3]);
        *(float4*)&sH[row*SZ_LD + C0 + 4] = make_float4(accf[r][4],accf[r][5],accf[r][6],accf[r][7]);
        if (tt == 31 && r == 7) {
            float* hp = g_h + (b * 16 + ty) * DP + C0;
            #pragma unroll
            for (int c = 0; c < 8; c++) hp[c] = accf[r][c];
        }
    }
    for (int idx = tid; idx < DP * DP; idx += 256) sW[idx] = g_WkT[idx];
    __syncthreads();

    zeroacc(acc2);
    gemmf2(acc2, sH, SZ_LD, sW, DP, R0, C0);
    #pragma unroll
    for (int r = 0; r < 8; r++) {
        int mm = b * 16 + ty;
        int tg = tt * 8 + r;
        float2 v0 = unp2(acc2[r][0]), v1 = unp2(acc2[r][1]);
        float2 v2 = unp2(acc2[r][2]), v3 = unp2(acc2[r][3]);
        uint4 o;
        o.x = bf2u(v0.x, v0.y);
        o.y = bf2u(v1.x, v1.y);
        o.z = bf2u(v2.x, v2.y);
        o.w = bf2u(v3.x, v3.y);
        *(uint4*)&g_Kh[(mm * Tt + tg) * DP + C0] = o;
    }
    __syncthreads();
    for (int idx = tid; idx < DP * DP; idx += 256) sW[idx] = g_WvT[idx];
    __syncthreads();

    zeroacc(acc2);
    gemmf2(acc2, sH, SZ_LD, sW, DP, R0, C0);
    #pragma unroll
    for (int r = 0; r < 8; r++) {
        int mm = b * 16 + ty;
        int tg = tt * 8 + r;
        float2 v0 = unp2(acc2[r][0]), v1 = unp2(acc2[r][1]);
        float2 v2 = unp2(acc2[r][2]), v3 = unp2(acc2[r][3]);
        uint4 o;
        o.x = bf2u(v0.x, v0.y);
        o.y = bf2u(v1.x, v1.y);
        o.z = bf2u(v2.x, v2.y);
        o.w = bf2u(v3.x, v3.y);
        *(uint4*)&g_Vh[(mm * Tt + tg) * DP + C0] = o;
    }
}

// ---- decoder: attention, 256 threads (8 blocks/SM -> single wave) ----
__global__ void __launch_bounds__(256) attn_kernel(const float* __restrict__ log_tau) {
    __shared__ __align__(16) float h_s[DP];
    __shared__ float al[Tt];
    __shared__ float sc[Tt];
    __shared__ float red[8], red2[8];
    __shared__ __align__(16) float part[16][132];
    int m = blockIdx.x, tid = threadIdx.x;
    int w = tid >> 5, lane = tid & 31;
    float scale = expf(log_tau[0]);
    if (tid < DP) h_s[tid] = g_h[m * DP + tid] * scale;
    if (tid >= 128 && tid < 144) {
        int c = tid - 128, b = m >> 4, i = m & 15;
        float s = 0.f;
        #pragma unroll
        for (int j = 0; j < 16; j++) s += g_A[b * 256 + i * 16 + j] * g_y[(b * 16 + j) * Cc + c];
        g_ymix[m * Cc + c] = g_y[m * Cc + c] + 0.3f * s;
    }
    __syncthreads();
    // scores: 8 warps x 32 t-rows, coalesced uint2 loads
    {
        float h0 = h_s[lane * 4], h1 = h_s[lane * 4 + 1];
        float h2 = h_s[lane * 4 + 2], h3 = h_s[lane * 4 + 3];
        #pragma unroll 4
        for (int r = 0; r < 32; r++) {
            int t = w * 32 + r;
            uint2 kv = *(const uint2*)(g_Kh + (m * Tt + t) * DP + lane * 4);
            float2 a0 = bfu2f(kv.x), a1 = bfu2f(kv.y);
            float dot = a0.x * h0 + a0.y * h1 + a1.x * h2 + a1.y * h3;
            #pragma unroll
            for (int o = 16; o; o >>= 1) dot += __shfl_xor_sync(0xffffffffu, dot, o);
            if (lane == 0) sc[t] = dot;
        }
    }
    __syncthreads();
    {
        float sv = sc[tid];
        float mx = sv;
        #pragma unroll
        for (int o = 16; o; o >>= 1) mx = fmaxf(mx, __shfl_xor_sync(0xffffffffu, mx, o));
        if ((tid & 31) == 0) red[tid >> 5] = mx;
    }
    __syncthreads();
    {
        float bmx = red[0];
        #pragma unroll
        for (int w2 = 1; w2 < 8; w2++) bmx = fmaxf(bmx, red[w2]);
        float ev = expf(sc[tid] - bmx);
        al[tid] = ev;
        float ss = ev;
        #pragma unroll
        for (int o = 16; o; o >>= 1) ss += __shfl_xor_sync(0xffffffffu, ss, o);
        if ((tid & 31) == 0) red2[tid >> 5] = ss;
    }
    __syncthreads();
    float tot = 0.f;
    #pragma unroll
    for (int w2 = 0; w2 < 8; w2++) tot += red2[w2];
    float inv = 1.f / tot;
    // ctx: 16 d-slices x 16 t-chunks of 16
    {
        int dsl = tid & 15, tch = tid >> 4;
        float acc[8];
        #pragma unroll
        for (int j = 0; j < 8; j++) acc[j] = 0.f;
        #pragma unroll 4
        for (int u = 0; u < 16; u++) {
            int t2 = tch * 16 + u;
            uint4 v = *(const uint4*)(g_Vh + (m * Tt + t2) * DP + dsl * 8);
            float a = al[t2];
            float2 f0 = bfu2f(v.x), f1 = bfu2f(v.y), f2 = bfu2f(v.z), f3 = bfu2f(v.w);
            acc[0] += a * f0.x; acc[1] += a * f0.y;
            acc[2] += a * f1.x; acc[3] += a * f1.y;
            acc[4] += a * f2.x; acc[5] += a * f2.y;
            acc[6] += a * f3.x; acc[7] += a * f3.y;
        }
        *(float4*)&part[tch][dsl * 8]     = make_float4(acc[0], acc[1], acc[2], acc[3]);
        *(float4*)&part[tch][dsl * 8 + 4] = make_float4(acc[4], acc[5], acc[6], acc[7]);
    }
    __syncthreads();
    if (tid < 128) {
        float c = 0.f;
        #pragma unroll
        for (int ch = 0; ch < 16; ch++) c += part[ch][tid];
        g_ctx[m * DP + tid] = c * inv;
    }
}

// ---- decoder: GRU cell + readout (f32x2) ----
__global__ void __launch_bounds__(384) cell_kernel(const float* __restrict__ Wihc,
                                                   const float* __restrict__ Whhc,
                                                   const float* __restrict__ bihc,
                                                   const float* __restrict__ bhhc,
                                                   const float* __restrict__ readW,
                                                   const float* __restrict__ readb,
                                                   const float* __restrict__ X,
                                                   float* __restrict__ out, int step) {
    __shared__ __align__(16) float inp[8 * 148];
    __shared__ __align__(16) float hprev[8 * 128];
    __shared__ float sX[384 * 8], sH2[384 * 8];
    __shared__ float shn[8 * 128];
    int m0 = blockIdx.x * 8, g = threadIdx.x;

    for (int idx = g; idx < 8 * 128; idx += 384) {
        int q = idx >> 7, d = idx & 127;
        inp[q * 148 + d] = g_ctx[(m0 + q) * DP + d];
        hprev[idx] = g_h[(m0 + q) * DP + d];
    }
    for (int idx = g; idx < 8 * 16; idx += 384) {
        int q = idx >> 4, c = idx & 15;
        inp[q * 148 + 128 + c] = g_ymix[(m0 + q) * Cc + c];
    }
    __syncthreads();

    ull aX2[8], aH2[8];
    #pragma unroll
    for (int q = 0; q < 8; q++) { aX2[q] = 0ull; aH2[q] = 0ull; }
    const ulonglong2* wr2 = (const ulonglong2*)(Wihc + g * 144);
    #pragma unroll 4
    for (int kk = 0; kk < 36; kk++) {
        ulonglong2 wv = wr2[kk];
        #pragma unroll
        for (int q = 0; q < 8; q++) {
            ulonglong2 iv = ((const ulonglong2*)(inp + q * 148))[kk];
            fma2(aX2[q], wv.x, iv.x);
            fma2(aX2[q], wv.y, iv.y);
        }
    }
    const ulonglong2* wh2 = (const ulonglong2*)(Whhc + g * 128);
    #pragma unroll 4
    for (int kk = 0; kk < 32; kk++) {
        ulonglong2 wv = wh2[kk];
        #pragma unroll
        for (int q = 0; q < 8; q++) {
            ulonglong2 hv = ((const ulonglong2*)(hprev + q * 128))[kk];
            fma2(aH2[q], wv.x, hv.x);
            fma2(aH2[q], wv.y, hv.y);
        }
    }
    float bi = bihc[g], bh = bhhc[g];
    #pragma unroll
    for (int q = 0; q < 8; q++) {
        float2 xv = unp2(aX2[q]), hv = unp2(aH2[q]);
        sX[g * 8 + q]  = bi + xv.x + xv.y;
        sH2[g * 8 + q] = bh + hv.x + hv.y;
    }
    __syncthreads();

    if (g < 128) {
        #pragma unroll
        for (int q = 0; q < 8; q++) {
            float r  = sigmoidf_(sX[g * 8 + q] + sH2[g * 8 + q]);
            float z  = sigmoidf_(sX[(g + 128) * 8 + q] + sH2[(g + 128) * 8 + q]);
            float nn = tanhf(sX[(g + 256) * 8 + q] + r * sH2[(g + 256) * 8 + q]);
            float hn = (1.f - z) * nn + z * hprev[q * 128 + g];
            g_h[(m0 + q) * DP + g] = hn;
            shn[q * 128 + g] = hn;
        }
    }
    __syncthreads();
    if (g < 128) {
        int q = g >> 4, c = g & 15;
        ull a2 = 0ull;
        const ulonglong2* rw2 = (const ulonglong2*)(readW + c * DP);
        const ulonglong2* hh2 = (const ulonglong2*)(shn + q * 128);
        #pragma unroll 8
        for (int kk = 0; kk < 32; kk++) {
            ulonglong2 wv = rw2[kk], hv = hh2[kk];
            fma2(a2, wv.x, hv.x);
            fma2(a2, wv.y, hv.y);
        }
        float2 av = unp2(a2);
        float yt = readb[c] + av.x + av.y + inp[q * 148 + 128 + c];
        int m = m0 + q;
        g_y[m * Cc + c] = yt;
        float yh = X[(m * Cc + c) * Tt + (Tt - 1)] + yt;
        out[(m * Cc + c) * TOUT + step] = yh;
        if (step == 0) out[BN * Cc * TOUT + m * Cc + c] = yh;
    }
}

extern "C" void kernel_launch(void* const* d_in, const int* in_sizes, int n_in,
                              void* d_out, int out_size) {
    const float* X      = (const float*)d_in[0];
    const int*   phases = (const int*)  d_in[1];
    const float* gWih   = (const float*)d_in[2];
    const float* gWhh   = (const float*)d_in[3];
    const float* gbih   = (const float*)d_in[4];
    const float* gbhh   = (const float*)d_in[5];
    const float* lng    = (const float*)d_in[6];
    const float* lnb    = (const float*)d_in[7];
    const float* tW     = (const float*)d_in[8];
    const float* tb     = (const float*)d_in[9];
    const float* S      = (const float*)d_in[10];
    const float* G      = (const float*)d_in[11];
    const float* Wself  = (const float*)d_in[12];
    const float* Wneigh = (const float*)d_in[13];
    const float* cWih   = (const float*)d_in[14];
    const float* cWhh   = (const float*)d_in[15];
    const float* cbih   = (const float*)d_in[16];
    const float* cbhh   = (const float*)d_in[17];
    const float* readW  = (const float*)d_in[18];
    const float* readb  = (const float*)d_in[19];
    const float* logtau = (const float*)d_in[22];
    float* out = (float*)d_out;

    cudaFuncSetAttribute(gru_kernel, cudaFuncAttributeMaxDynamicSharedMemorySize, GRU_SMEM);
    cudaFuncSetAttribute(feat_kernel, cudaFuncAttributeMaxDynamicSharedMemorySize, FEAT_SMEM);

    spec_kernel<<<1, 256>>>(Wneigh);
    prep_kernel<<<68, 256>>>(Wself, (const float*)d_in[20], (const float*)d_in[21]);
    graph_kernel<<<Bb, 256>>>(S, G, phases);
    gru_kernel<<<128, 384, GRU_SMEM>>>(X, gWih, gWhh, gbih, gbhh, lng, lnb);
    feat_kernel<<<Bb * 32, 256, FEAT_SMEM>>>(tW, tb);
    for (int s = 0; s < TOUT; s++) {
        attn_kernel<<<BN, 256>>>(logtau);
        cell_kernel<<<BN / 8, 384>>>(cWih, cWhh, cbih, cbhh, readW, readb, X, out, s);
    }
}